// round 10
// baseline (speedup 1.0000x reference)
#include <cuda_runtime.h>

#define NF 39
#define NV 200000
#define NB 16384
#define RPB 32              // rows per block
#define NT 256              // 8 warps x 4 rows
#define GRID (NB / RPB)     // 512

// ---------- f32x2 helpers ----------
static __device__ __forceinline__ unsigned long long pack2(float a, float b) {
    unsigned long long r;
    asm("mov.b64 %0, {%1, %2};" : "=l"(r) : "f"(a), "f"(b));
    return r;
}
static __device__ __forceinline__ void ffma2(unsigned long long& acc,
                                             unsigned long long a,
                                             unsigned long long b) {
    asm("fma.rn.f32x2 %0, %1, %2, %0;" : "+l"(acc) : "l"(a), "l"(b));
}
static __device__ __forceinline__ void unpack2(unsigned long long v, float& lo, float& hi) {
    asm("mov.b64 {%0, %1}, %2;" : "=f"(lo), "=f"(hi) : "l"(v));
}

// transposed packed weights: [f][j=e-pair][d] -> { (W1[d,f,2j],W1[d,f,2j+1]), (Wi pair) }
static __device__ ulonglong2 g_wt[NF * 8 * 32];   // 160KB

__global__ void __launch_bounds__(256)
prep_wt(const float* __restrict__ W1, const float* __restrict__ Wi)
{
    int i = blockIdx.x * blockDim.x + threadIdx.x;
    if (i >= 32 * 312) return;
    int d = i / 312;
    int rem = i - d * 312;
    int f = rem >> 3, j = rem & 7;
    const float* p1 = W1 + d * (NF * 16) + f * 16 + 2 * j;
    const float* pi = Wi + d * (NF * 16) + f * 16 + 2 * j;
    ulonglong2 v;
    v.x = pack2(p1[0], p1[1]);
    v.y = pack2(pi[0], pi[1]);
    g_wt[(f * 8 + j) * 32 + d] = v;
}

// ---------- smem layout (bytes) ----------
#define OFF_EST  0          // 8 warps x 2 phases x 32 ULL (transposed emb) = 4096
#define OFF_XIS  4096       // 32*39 int   = 4992
#define OFF_XVS  9088       // 32*39 float = 4992
#define OFF_MLP  14080      // 2176 floats = 8704
#define OFF_XB   22784      // 32*33 floats = 4224
#define OFF_YB   27008      // 4224
#define SMEM_TOT 31232

extern __shared__ unsigned char smem_raw[];

__global__ void __launch_bounds__(NT, 4)
pnn_main(const int* __restrict__ Xi, const float* __restrict__ Xv,
         const float* __restrict__ tables,
         const float* __restrict__ l1w, const float* __restrict__ l1b,
         const float* __restrict__ l2w, const float* __restrict__ l2b,
         const float* __restrict__ lw, const float* __restrict__ lb,
         float* __restrict__ out)
{
    unsigned long long* est = reinterpret_cast<unsigned long long*>(smem_raw + OFF_EST);
    int*   Xis = reinterpret_cast<int*>(smem_raw + OFF_XIS);
    float* Xvs = reinterpret_cast<float*>(smem_raw + OFF_XVS);
    float* mlp = reinterpret_cast<float*>(smem_raw + OFF_MLP);
    float* xb  = reinterpret_cast<float*>(smem_raw + OFF_XB);
    float* yb  = reinterpret_cast<float*>(smem_raw + OFF_YB);

    const int tid = threadIdx.x;
    const int w = tid >> 5, lane = tid & 31;

    // ---- stage Xi/Xv slice + MLP weights ----
    {
        const long gbase = (long)blockIdx.x * RPB * NF;
        for (int i = tid; i < RPB * NF; i += NT) { Xis[i] = Xi[gbase + i]; Xvs[i] = Xv[gbase + i]; }
        for (int i = tid; i < 1024; i += NT) { mlp[i] = l1w[i]; mlp[1024 + i] = l2w[i]; }
        if (tid < 32) {
            mlp[2048 + tid] = l1b[tid];
            mlp[2080 + tid] = l2b[tid];
            mlp[2112 + tid] = lw[tid];
            if (tid == 0) mlp[2144] = lb[0];
        }
    }
    __syncthreads();

    // warp-private transposed emb buffer: eb[p*32 + j*4 + r]
    unsigned long long* eb = est + w * 64;
    const int gr = lane >> 3, gj = lane & 7;        // gather: row-in-warp, e-pair
    const int lr = w * 4 + gr;                      // local row of this lane's gather
    const ulonglong2* wt = g_wt + lane;             // lane = d

    // ---- prologue: gather field 0 (transposed) into phase 0 ----
    {
        int   idx = Xis[lr * NF];
        float v   = Xvs[lr * NF];
        float2 t = __ldcg(reinterpret_cast<const float2*>(tables + ((long)idx) * 16) + gj);
        eb[gj * 4 + gr] = pack2(t.x * v, t.y * v);
    }
    __syncwarp();

    unsigned long long accfo[4] = {0ull, 0ull, 0ull, 0ull};
    unsigned long long accs[4]  = {0ull, 0ull, 0ull, 0ull};

    ulonglong2 w0 = wt[0];                          // (f=0, j=0) weight, prefetched

    for (int f = 0; f < NF; f++) {
        const int p = f & 1;
        const bool pf = (f + 1 < NF);

        // ---- prefetch next field: gather + first weight ----
        float2 tn; float vn = 0.0f;
        if (pf) {
            int idx = Xis[lr * NF + f + 1];
            vn = Xvs[lr * NF + f + 1];
            tn = __ldcg(reinterpret_cast<const float2*>(
                     tables + ((long)(f + 1) * NV + idx) * 16) + gj);
        }
        ulonglong2 w0n = pf ? wt[(f + 1) * 256] : w0;

        // ---- compute field f: j-outer, weights pipelined, emb broadcast ----
        {
            const ulonglong2* ep = reinterpret_cast<const ulonglong2*>(eb + p * 32);
            const ulonglong2* wp = wt + f * 256;
            ulonglong2 wv = w0;
#pragma unroll
            for (int j = 0; j < 8; j++) {
                ulonglong2 wn = (j < 7) ? wp[(j + 1) * 32] : w0n;
                ulonglong2 e01 = ep[j * 2];         // rows 0,1 (broadcast LDS.128)
                ulonglong2 e23 = ep[j * 2 + 1];     // rows 2,3
                ffma2(accfo[0], e01.x, wv.x); ffma2(accs[0], e01.x, wv.y);
                ffma2(accfo[1], e01.y, wv.x); ffma2(accs[1], e01.y, wv.y);
                ffma2(accfo[2], e23.x, wv.x); ffma2(accs[2], e23.x, wv.y);
                ffma2(accfo[3], e23.y, wv.x); ffma2(accs[3], e23.y, wv.y);
                wv = wn;
            }
            w0 = w0n;
        }

        // ---- stage prefetched gather (transposed) ----
        if (pf) {
            eb[(p ^ 1) * 32 + gj * 4 + gr] = pack2(tn.x * vn, tn.y * vn);
        }
        __syncwarp();
    }

    // ---- x = fo + s^2 ; lane = d ----
#pragma unroll
    for (int r = 0; r < 4; r++) {
        float a, b;
        unpack2(accfo[r], a, b); float fo = a + b;
        unpack2(accs[r],  a, b); float sv = a + b;
        xb[(w * 4 + r) * 33 + lane] = fmaf(sv, sv, fo);
    }
    __syncthreads();

    // ---- MLP: 8 threads per row, 4 outputs each ----
    const int q = tid & 7, rr = tid >> 3;
    {
        const float* xr = xb + rr * 33;
#pragma unroll
        for (int j = 0; j < 4; j++) {
            int jj = q * 4 + j;
            float s = mlp[2048 + jj];
            const float* wrow = mlp + jj * 32;
#pragma unroll
            for (int k = 0; k < 32; k++) s = fmaf(xr[k], wrow[k], s);
            yb[rr * 33 + jj] = fmaxf(s, 0.0f);
        }
    }
    __syncthreads();
    {
        const float* yr = yb + rr * 33;
#pragma unroll
        for (int j = 0; j < 4; j++) {
            int jj = q * 4 + j;
            float s = mlp[2080 + jj];
            const float* wrow = mlp + 1024 + jj * 32;
#pragma unroll
            for (int k = 0; k < 32; k++) s = fmaf(yr[k], wrow[k], s);
            xb[rr * 33 + jj] = fmaxf(s, 0.0f);
        }
    }
    __syncthreads();
    if (q == 0) {
        float s = mlp[2144];
        const float* zr = xb + rr * 33;
#pragma unroll
        for (int k = 0; k < 32; k++) s = fmaf(zr[k], mlp[2112 + k], s);
        out[blockIdx.x * RPB + rr] = s;
    }
}

extern "C" void kernel_launch(void* const* d_in, const int* in_sizes, int n_in,
                              void* d_out, int out_size)
{
    const int*   Xi     = (const int*)  d_in[0];
    const float* Xv     = (const float*)d_in[1];
    const float* tables = (const float*)d_in[2];
    const float* W1     = (const float*)d_in[3];
    const float* Wi     = (const float*)d_in[4];
    const float* l1w    = (const float*)d_in[5];
    const float* l1b    = (const float*)d_in[6];
    const float* l2w    = (const float*)d_in[7];
    const float* l2b    = (const float*)d_in[8];
    const float* lw     = (const float*)d_in[9];
    const float* lb     = (const float*)d_in[10];

    prep_wt<<<(32 * 312 + 255) / 256, 256>>>(W1, Wi);

    cudaFuncSetAttribute(pnn_main, cudaFuncAttributeMaxDynamicSharedMemorySize, SMEM_TOT);
    pnn_main<<<GRID, NT, SMEM_TOT>>>(
        Xi, Xv, tables, l1w, l1b, l2w, l2b, lw, lb, (float*)d_out);
}

// round 11
// speedup vs baseline: 1.7178x; 1.7178x over previous
#include <cuda_runtime.h>
#include <cuda_bf16.h>

#define NF 39
#define NV 200000
#define NB 16384
#define RPB 64              // rows per CTA
#define NT 128              // 4 warps
#define GRID (NB / RPB)     // 256
#define GROUPS 10           // 4 fields per group, K=64 per group

// B (weights) pre-transposed: plane(hi/lo) x n(64) x k(640, zero-padded past 624), bf16
static __device__ __align__(16) __nv_bfloat16 g_wg[2 * 64 * 640];

__global__ void __launch_bounds__(256)
prep_wg(const float* __restrict__ W1, const float* __restrict__ Wi)
{
    int i = blockIdx.x * blockDim.x + threadIdx.x;
    if (i >= 64 * 640) return;
    int n = i / 640, k = i - n * 640;
    float val = 0.0f;
    if (k < 624) {
        int f = k >> 4, e = k & 15;
        val = (n < 32) ? W1[n * 624 + f * 16 + e] : Wi[(n - 32) * 624 + f * 16 + e];
    }
    __nv_bfloat16 hi = __float2bfloat16(val);
    __nv_bfloat16 lo = __float2bfloat16(val - __bfloat162float(hi));
    g_wg[i] = hi;                   // plane 0
    g_wg[64 * 640 + i] = lo;        // plane 1
}

// ---------- mma m16n8k16 bf16 ----------
static __device__ __forceinline__ void mma_bf16(float* c, const unsigned* a,
                                                unsigned b0, unsigned b1) {
    asm("mma.sync.aligned.m16n8k16.row.col.f32.bf16.bf16.f32 "
        "{%0,%1,%2,%3}, {%4,%5,%6,%7}, {%8,%9}, {%0,%1,%2,%3};"
        : "+f"(c[0]), "+f"(c[1]), "+f"(c[2]), "+f"(c[3])
        : "r"(a[0]), "r"(a[1]), "r"(a[2]), "r"(a[3]), "r"(b0), "r"(b1));
}

// ---------- smem layout (bytes) ----------
// A planes: 64 rows x 36 words (64 bf16 + pad) -> frag LDS banks (l/4)*4 + l%4: conflict-free
#define A_HI 0
#define A_LO 9216
#define B_HI 18432
#define B_LO 27648
#define OFF_MLP 36864       // 2176 floats
#define SMEM_TOT 45568
// epilogue aliases:
#define OFF_XD A_HI         // 64 x 66 floats = 16896 <= 18432
#define OFF_XB B_HI         // 64 x 33 floats = 8448
#define OFF_YB B_LO         // 8448

extern __shared__ unsigned char smem_raw[];

__global__ void __launch_bounds__(NT, 4)
pnn_mma(const int* __restrict__ Xi, const float* __restrict__ Xv,
        const float* __restrict__ tables,
        const float* __restrict__ l1w, const float* __restrict__ l1b,
        const float* __restrict__ l2w, const float* __restrict__ l2b,
        const float* __restrict__ lw, const float* __restrict__ lb,
        float* __restrict__ out)
{
    const int tid = threadIdx.x;
    const int w = tid >> 5, l = tid & 31;
    const int qr = l >> 2, ql = l & 3;
    const int row0 = blockIdx.x * RPB;

    float* mlp = reinterpret_cast<float*>(smem_raw + OFF_MLP);
    const unsigned* Ah = reinterpret_cast<const unsigned*>(smem_raw + A_HI);
    const unsigned* Al = reinterpret_cast<const unsigned*>(smem_raw + A_LO);
    const unsigned* Bh = reinterpret_cast<const unsigned*>(smem_raw + B_HI);
    const unsigned* Bl = reinterpret_cast<const unsigned*>(smem_raw + B_LO);

    // ---- stage MLP weights ----
    for (int i = tid; i < 1024; i += NT) { mlp[i] = l1w[i]; mlp[1024 + i] = l2w[i]; }
    if (tid < 32) {
        mlp[2048 + tid] = l1b[tid];
        mlp[2080 + tid] = l2b[tid];
        mlp[2112 + tid] = lw[tid];
        if (tid == 0) mlp[2144] = lb[0];
    }

    // gather unit mapping: units u = tid, tid+128; u -> (row = u>>2, fl = u&3)
    const int r0 = tid >> 2, fl0 = tid & 3;
    const int r1 = (tid + 128) >> 2, fl1 = fl0;
    const float4* tab4 = reinterpret_cast<const float4*>(tables);

    float4 aq[2][4]; float av[2];

    // ---- gather group 0 ----
#pragma unroll
    for (int i = 0; i < 2; i++) {
        int row = i ? r1 : r0, fl = i ? fl1 : fl0;
        int f = fl;   // group 0
        int idx = Xi[(row0 + row) * NF + f];
        av[i] = Xv[(row0 + row) * NF + f];
        const float4* s = tab4 + ((long)f * NV + idx) * 4;
        aq[i][0] = s[0]; aq[i][1] = s[1]; aq[i][2] = s[2]; aq[i][3] = s[3];
    }

    // ---- stage helper lambdas (manual) ----
    // B stage for group g: thread -> (plane = tid>>6, n = tid&63), 8 uint4 of 16B
    // A stage: split+scale 16 floats -> hi/lo words, 2+2 STS.128 per unit

    float acc[8][4];
#pragma unroll
    for (int nb = 0; nb < 8; nb++)
#pragma unroll
        for (int j = 0; j < 4; j++) acc[nb][j] = 0.0f;

    // ---- prologue: stage group 0 tiles ----
    {
        // B
        const int plane = tid >> 6, n = tid & 63;
        const uint4* src = reinterpret_cast<const uint4*>(g_wg) + ((plane * 64 + n) * 80);
        unsigned char* dst = smem_raw + (plane ? B_LO : B_HI) + n * 144;
#pragma unroll
        for (int j = 0; j < 8; j++)
            *reinterpret_cast<uint4*>(dst + j * 16) = src[j];
        // A
#pragma unroll
        for (int i = 0; i < 2; i++) {
            int row = i ? r1 : r0, fl = i ? fl1 : fl0;
            float v = av[i];
            float x[16];
#pragma unroll
            for (int j = 0; j < 4; j++) {
                float4 q = aq[i][j];
                x[4*j] = q.x*v; x[4*j+1] = q.y*v; x[4*j+2] = q.z*v; x[4*j+3] = q.w*v;
            }
            unsigned hw[8], lw2[8];
#pragma unroll
            for (int j = 0; j < 8; j++) {
                __nv_bfloat162 h2 = __floats2bfloat162_rn(x[2*j], x[2*j+1]);
                float ra = x[2*j]   - __bfloat162float(h2.x);
                float rb = x[2*j+1] - __bfloat162float(h2.y);
                __nv_bfloat162 l2 = __floats2bfloat162_rn(ra, rb);
                hw[j]  = *reinterpret_cast<unsigned*>(&h2);
                lw2[j] = *reinterpret_cast<unsigned*>(&l2);
            }
            unsigned boff = (row * 36 + fl * 8) * 4;
            *reinterpret_cast<uint4*>(smem_raw + A_HI + boff)      = make_uint4(hw[0], hw[1], hw[2], hw[3]);
            *reinterpret_cast<uint4*>(smem_raw + A_HI + boff + 16) = make_uint4(hw[4], hw[5], hw[6], hw[7]);
            *reinterpret_cast<uint4*>(smem_raw + A_LO + boff)      = make_uint4(lw2[0], lw2[1], lw2[2], lw2[3]);
            *reinterpret_cast<uint4*>(smem_raw + A_LO + boff + 16) = make_uint4(lw2[4], lw2[5], lw2[6], lw2[7]);
        }
    }
    __syncthreads();

    for (int g = 0; g < GROUPS; g++) {
        const bool pf = (g + 1 < GROUPS);

        // ---- issue next group's A gather (overlaps compute) ----
        if (pf) {
#pragma unroll
            for (int i = 0; i < 2; i++) {
                int row = i ? r1 : r0, fl = i ? fl1 : fl0;
                int f = (g + 1) * 4 + fl;
                if (f < NF) {
                    int idx = Xi[(row0 + row) * NF + f];
                    av[i] = Xv[(row0 + row) * NF + f];
                    const float4* s = tab4 + ((long)f * NV + idx) * 4;
                    aq[i][0] = s[0]; aq[i][1] = s[1]; aq[i][2] = s[2]; aq[i][3] = s[3];
                } else {
                    av[i] = 0.0f;
                    aq[i][0] = aq[i][1] = aq[i][2] = aq[i][3] = make_float4(0.f, 0.f, 0.f, 0.f);
                }
            }
        }

        // ---- compute: 4 k-steps x 8 n-blocks x 3 passes ----
        {
            const int abase = (w * 16 + qr) * 36 + ql;
#pragma unroll
            for (int ks = 0; ks < 4; ks++) {
                const int ao = abase + ks * 8;
                unsigned ahi[4], alo[4];
                ahi[0] = Ah[ao];       ahi[1] = Ah[ao + 288];
                ahi[2] = Ah[ao + 4];   ahi[3] = Ah[ao + 292];
                alo[0] = Al[ao];       alo[1] = Al[ao + 288];
                alo[2] = Al[ao + 4];   alo[3] = Al[ao + 292];
#pragma unroll
                for (int nb = 0; nb < 8; nb++) {
                    const int bo = (nb * 8 + qr) * 36 + ks * 8 + ql;
                    unsigned bh0 = Bh[bo], bh1 = Bh[bo + 4];
                    unsigned bl0 = Bl[bo], bl1 = Bl[bo + 4];
                    mma_bf16(acc[nb], ahi, bh0, bh1);
                    mma_bf16(acc[nb], alo, bh0, bh1);
                    mma_bf16(acc[nb], ahi, bl0, bl1);
                }
            }
        }
        __syncthreads();

        // ---- stage next group's tiles ----
        if (pf) {
            const int plane = tid >> 6, n = tid & 63;
            const uint4* src = reinterpret_cast<const uint4*>(g_wg) +
                               ((plane * 64 + n) * 80 + (g + 1) * 8);
            uint4 bu[8];
#pragma unroll
            for (int j = 0; j < 8; j++) bu[j] = src[j];

#pragma unroll
            for (int i = 0; i < 2; i++) {
                int row = i ? r1 : r0, fl = i ? fl1 : fl0;
                float v = av[i];
                float x[16];
#pragma unroll
                for (int j = 0; j < 4; j++) {
                    float4 q = aq[i][j];
                    x[4*j] = q.x*v; x[4*j+1] = q.y*v; x[4*j+2] = q.z*v; x[4*j+3] = q.w*v;
                }
                unsigned hw[8], lw2[8];
#pragma unroll
                for (int j = 0; j < 8; j++) {
                    __nv_bfloat162 h2 = __floats2bfloat162_rn(x[2*j], x[2*j+1]);
                    float ra = x[2*j]   - __bfloat162float(h2.x);
                    float rb = x[2*j+1] - __bfloat162float(h2.y);
                    __nv_bfloat162 l2 = __floats2bfloat162_rn(ra, rb);
                    hw[j]  = *reinterpret_cast<unsigned*>(&h2);
                    lw2[j] = *reinterpret_cast<unsigned*>(&l2);
                }
                unsigned boff = (row * 36 + fl * 8) * 4;
                *reinterpret_cast<uint4*>(smem_raw + A_HI + boff)      = make_uint4(hw[0], hw[1], hw[2], hw[3]);
                *reinterpret_cast<uint4*>(smem_raw + A_HI + boff + 16) = make_uint4(hw[4], hw[5], hw[6], hw[7]);
                *reinterpret_cast<uint4*>(smem_raw + A_LO + boff)      = make_uint4(lw2[0], lw2[1], lw2[2], lw2[3]);
                *reinterpret_cast<uint4*>(smem_raw + A_LO + boff + 16) = make_uint4(lw2[4], lw2[5], lw2[6], lw2[7]);
            }
            unsigned char* dst = smem_raw + (plane ? B_LO : B_HI) + n * 144;
#pragma unroll
            for (int j = 0; j < 8; j++)
                *reinterpret_cast<uint4*>(dst + j * 16) = bu[j];
            __syncthreads();
        }
    }
    __syncthreads();   // all reads of A/B done; safe to alias

    // ---- dump D to xd[64][66] ----
    float* xd = reinterpret_cast<float*>(smem_raw + OFF_XD);
    {
        const int rA = w * 16 + qr, rB = rA + 8;
#pragma unroll
        for (int nb = 0; nb < 8; nb++) {
            int c = nb * 8 + 2 * ql;
            *reinterpret_cast<float2*>(xd + rA * 66 + c) = make_float2(acc[nb][0], acc[nb][1]);
            *reinterpret_cast<float2*>(xd + rB * 66 + c) = make_float2(acc[nb][2], acc[nb][3]);
        }
    }
    __syncthreads();

    // ---- x = fo + s^2 ----
    float* xb = reinterpret_cast<float*>(smem_raw + OFF_XB);
    float* yb = reinterpret_cast<float*>(smem_raw + OFF_YB);
    {
        const int rr = tid >> 1, hh = tid & 1;
#pragma unroll
        for (int j = 0; j < 16; j++) {
            int d = hh * 16 + j;
            float fo = xd[rr * 66 + d];
            float sv = xd[rr * 66 + 32 + d];
            xb[rr * 33 + d] = fmaf(sv, sv, fo);
        }
    }
    __syncthreads();

    // ---- MLP: 2 threads/row, 16 outputs each ----
    const int rr = tid >> 1, hh = tid & 1;
    {
        const float* xr = xb + rr * 33;
#pragma unroll
        for (int j = 0; j < 16; j++) {
            int jj = hh * 16 + j;
            float s = mlp[2048 + jj];
            const float* wrow = mlp + jj * 32;
#pragma unroll
            for (int k = 0; k < 32; k++) s = fmaf(xr[k], wrow[k], s);
            yb[rr * 33 + jj] = fmaxf(s, 0.0f);
        }
    }
    __syncthreads();
    {
        const float* yr = yb + rr * 33;
#pragma unroll
        for (int j = 0; j < 16; j++) {
            int jj = hh * 16 + j;
            float s = mlp[2080 + jj];
            const float* wrow = mlp + 1024 + jj * 32;
#pragma unroll
            for (int k = 0; k < 32; k++) s = fmaf(yr[k], wrow[k], s);
            xb[rr * 33 + jj] = fmaxf(s, 0.0f);
        }
    }
    __syncthreads();
    if (hh == 0) {
        float s = mlp[2144];
        const float* zr = xb + rr * 33;
#pragma unroll
        for (int k = 0; k < 32; k++) s = fmaf(zr[k], mlp[2112 + k], s);
        out[row0 + rr] = s;
    }
}

extern "C" void kernel_launch(void* const* d_in, const int* in_sizes, int n_in,
                              void* d_out, int out_size)
{
    const int*   Xi     = (const int*)  d_in[0];
    const float* Xv     = (const float*)d_in[1];
    const float* tables = (const float*)d_in[2];
    const float* W1     = (const float*)d_in[3];
    const float* Wi     = (const float*)d_in[4];
    const float* l1w    = (const float*)d_in[5];
    const float* l1b    = (const float*)d_in[6];
    const float* l2w    = (const float*)d_in[7];
    const float* l2b    = (const float*)d_in[8];
    const float* lw     = (const float*)d_in[9];
    const float* lb     = (const float*)d_in[10];

    prep_wg<<<(64 * 640 + 255) / 256, 256>>>(W1, Wi);

    cudaFuncSetAttribute(pnn_mma, cudaFuncAttributeMaxDynamicSharedMemorySize, SMEM_TOT);
    pnn_mma<<<GRID, NT, SMEM_TOT>>>(
        Xi, Xv, tables, l1w, l1b, l2w, l2b, lw, lb, (float*)d_out);
}